// round 1
// baseline (speedup 1.0000x reference)
#include <cuda_runtime.h>
#include <cuda_bf16.h>
#include <math.h>

// HashedInterpolator: 3-D hash-grid trilinear interpolation.
// position: [B, 3] f32 in [0,1);  hash_table: [524288, 4] f32;  out: [B, 4] f32.
//
// hash(corner) = (x*1 ^ y*19349663 ^ z*83492791) & (2^19 - 1)   (int32 wrap)
// weights: bit 0 -> frac = (pos - lower/512)*512 ; bit 1 -> (upper/512 - pos)*512
// (this matches the reference's coef indexing exactly).

#define HG_ENTRIES 524288
#define HG_MASK    (HG_ENTRIES - 1)
#define HG_P1      19349663u
#define HG_P2      83492791u

__global__ __launch_bounds__(256) void hashed_interp_kernel(
    const float* __restrict__ pos,
    const float4* __restrict__ table,
    float4* __restrict__ out,
    int batch)
{
    int i = blockIdx.x * blockDim.x + threadIdx.x;
    if (i >= batch) return;

    float px = pos[3 * i + 0];
    float py = pos[3 * i + 1];
    float pz = pos[3 * i + 2];

    int lx = (int)floorf(px * 512.0f);
    int ly = (int)floorf(py * 512.0f);
    int lz = (int)floorf(pz * 512.0f);

    const float inv = 1.0f / 512.0f;   // exact
    // bit 0 -> (pos - ll)/size ; bit 1 -> (ul - pos)/size ; size == 1/512 exactly.
    float wx0 = (px - (float)lx * inv) * 512.0f;
    float wx1 = ((float)(lx + 1) * inv - px) * 512.0f;
    float wy0 = (py - (float)ly * inv) * 512.0f;
    float wy1 = ((float)(ly + 1) * inv - py) * 512.0f;
    float wz0 = (pz - (float)lz * inv) * 512.0f;
    float wz1 = ((float)(lz + 1) * inv - pz) * 512.0f;

    unsigned hx0 = (unsigned)lx;
    unsigned hx1 = (unsigned)(lx + 1);
    unsigned hy0 = (unsigned)ly * HG_P1;
    unsigned hy1 = (unsigned)(ly + 1) * HG_P1;
    unsigned hz0 = (unsigned)lz * HG_P2;
    unsigned hz1 = (unsigned)(lz + 1) * HG_P2;

    // corner order = itertools.product bits (bx,by,bz); order irrelevant (sum).
    unsigned i000 = (hx0 ^ hy0 ^ hz0) & HG_MASK;
    unsigned i001 = (hx0 ^ hy0 ^ hz1) & HG_MASK;
    unsigned i010 = (hx0 ^ hy1 ^ hz0) & HG_MASK;
    unsigned i011 = (hx0 ^ hy1 ^ hz1) & HG_MASK;
    unsigned i100 = (hx1 ^ hy0 ^ hz0) & HG_MASK;
    unsigned i101 = (hx1 ^ hy0 ^ hz1) & HG_MASK;
    unsigned i110 = (hx1 ^ hy1 ^ hz0) & HG_MASK;
    unsigned i111 = (hx1 ^ hy1 ^ hz1) & HG_MASK;

    // Issue all 8 independent gathers up front (MLP=8) to hide L2 latency.
    float4 v000 = __ldg(&table[i000]);
    float4 v001 = __ldg(&table[i001]);
    float4 v010 = __ldg(&table[i010]);
    float4 v011 = __ldg(&table[i011]);
    float4 v100 = __ldg(&table[i100]);
    float4 v101 = __ldg(&table[i101]);
    float4 v110 = __ldg(&table[i110]);
    float4 v111 = __ldg(&table[i111]);

    float w000 = wx0 * wy0 * wz0;
    float w001 = wx0 * wy0 * wz1;
    float w010 = wx0 * wy1 * wz0;
    float w011 = wx0 * wy1 * wz1;
    float w100 = wx1 * wy0 * wz0;
    float w101 = wx1 * wy0 * wz1;
    float w110 = wx1 * wy1 * wz0;
    float w111 = wx1 * wy1 * wz1;

    float4 acc;
    acc.x = v000.x * w000;
    acc.y = v000.y * w000;
    acc.z = v000.z * w000;
    acc.w = v000.w * w000;

    acc.x = fmaf(v001.x, w001, acc.x);
    acc.y = fmaf(v001.y, w001, acc.y);
    acc.z = fmaf(v001.z, w001, acc.z);
    acc.w = fmaf(v001.w, w001, acc.w);

    acc.x = fmaf(v010.x, w010, acc.x);
    acc.y = fmaf(v010.y, w010, acc.y);
    acc.z = fmaf(v010.z, w010, acc.z);
    acc.w = fmaf(v010.w, w010, acc.w);

    acc.x = fmaf(v011.x, w011, acc.x);
    acc.y = fmaf(v011.y, w011, acc.y);
    acc.z = fmaf(v011.z, w011, acc.z);
    acc.w = fmaf(v011.w, w011, acc.w);

    acc.x = fmaf(v100.x, w100, acc.x);
    acc.y = fmaf(v100.y, w100, acc.y);
    acc.z = fmaf(v100.z, w100, acc.z);
    acc.w = fmaf(v100.w, w100, acc.w);

    acc.x = fmaf(v101.x, w101, acc.x);
    acc.y = fmaf(v101.y, w101, acc.y);
    acc.z = fmaf(v101.z, w101, acc.z);
    acc.w = fmaf(v101.w, w101, acc.w);

    acc.x = fmaf(v110.x, w110, acc.x);
    acc.y = fmaf(v110.y, w110, acc.y);
    acc.z = fmaf(v110.z, w110, acc.z);
    acc.w = fmaf(v110.w, w110, acc.w);

    acc.x = fmaf(v111.x, w111, acc.x);
    acc.y = fmaf(v111.y, w111, acc.y);
    acc.z = fmaf(v111.z, w111, acc.z);
    acc.w = fmaf(v111.w, w111, acc.w);

    out[i] = acc;
}

extern "C" void kernel_launch(void* const* d_in, const int* in_sizes, int n_in,
                              void* d_out, int out_size)
{
    const float* pos = (const float*)d_in[0];
    const float4* table = (const float4*)d_in[1];
    float4* out = (float4*)d_out;
    int batch = in_sizes[0] / 3;

    int threads = 256;
    int blocks = (batch + threads - 1) / threads;
    hashed_interp_kernel<<<blocks, threads>>>(pos, table, out, batch);
}